// round 14
// baseline (speedup 1.0000x reference)
#include <cuda_runtime.h>
#include <math.h>

#define NT 256
#define FTS 98    // ftp row stride in u64 (784B)
typedef unsigned long long u64;

__device__ __forceinline__ u64 pk2(float lo, float hi) {
    u64 r; asm("mov.b64 %0,{%1,%2};" : "=l"(r) : "f"(lo), "f"(hi)); return r;
}
__device__ __forceinline__ void upk2(u64 v, float& lo, float& hi) {
    asm("mov.b64 {%0,%1},%2;" : "=f"(lo), "=f"(hi) : "l"(v));
}
__device__ __forceinline__ void fma2(u64& d, u64 a, u64 b) {
    asm("fma.rn.f32x2 %0,%1,%2,%0;" : "+l"(d) : "l"(a), "l"(b));
}
__device__ __forceinline__ float hsum2(u64 v) {
    float lo, hi; upk2(v, lo, hi); return lo + hi;
}
__device__ __forceinline__ float fast_tanh(float x) {
    float t, r;
    asm("ex2.approx.f32 %0, %1;" : "=f"(t) : "f"(x * 2.885390082f));
    asm("rcp.approx.f32 %0, %1;" : "=f"(r) : "f"(t + 1.0f));
    return 1.0f - 2.0f * r;
}

struct __align__(16) Smem {
    union {
        float xs[3 * 34 * 34];       // phases 1-2 (13872B)
        u64   wcfp[16 * 64];         // depth loop: [icp][chunk][half][o8] pairs (8192B)
    } A;
    union {
        float p1p[8 * 17 * 17];      // phases 2-3 (9248B)
        struct { u64 weffp[16 * 32]; float beff[32]; } L;  // depth loop (4224B)
    } B;
    union {
        float p2[16 * 49];           // phases 3-4 (3136B)
        struct { float red[8]; float clsred[80]; } R;      // depth loop + classifier
    } C;
    u64    ftp[16 * FTS];            // feature map [icp][pos], pos = y*10+x (12544B)
    float2 w1d[600];                 // conv1 [tap][oc8] dup pairs (4800B)
    float  w2f[72 * 16];             // conv2 [tap][oc] plain floats (4608B)
    u64    w3p[8 * 32];              // conv3 [icp][j][half] interleaved (2048B)
    float  wcfcT[16 * 64];           // conf fc weights transposed [pooledpos][oc] (4096B)
    float  bcf[64];
    float  b1[8], b2[16], b3[32];
    float  bcfc;
};

__global__ __launch_bounds__(NT, 4)
void TM_20005957665089_kernel(
    const float* __restrict__ gx,
    const float* __restrict__ gw1,  const float* __restrict__ gb1,
    const float* __restrict__ gw2,  const float* __restrict__ gb2,
    const float* __restrict__ gw3,  const float* __restrict__ gb3,
    const float* __restrict__ gwcf, const float* __restrict__ gbcf,
    const float* __restrict__ gwcfc,const float* __restrict__ gbcfc,
    const float* __restrict__ gwq,  const float* __restrict__ gbq,
    const float* __restrict__ gwa,  const float* __restrict__ gba,
    const float* __restrict__ gwcls,const float* __restrict__ gbcls,
    float* __restrict__ gout)
{
    extern __shared__ float smem_raw[];
    Smem* s = reinterpret_cast<Smem*>(smem_raw);
    const int tid  = threadIdx.x;
    const int lane = tid & 31;
    const int wid  = tid >> 5;
    const int b    = blockIdx.x;

    // ---- Phase 0: border-only zeroing + weight staging ----
    for (int i = tid; i < 408; i += NT) {   // xs border ring (interior overwritten)
        int ch = i / 136, k = i % 136, seg = k / 34, t = k % 34;
        int off = (seg == 0) ? t : (seg == 1) ? 33*34 + t : (seg == 2) ? t*34 : t*34 + 33;
        s->A.xs[ch * 1156 + off] = 0.f;
    }
    for (int i = tid; i < 544; i += NT) {   // p1p border ring
        int ch = i / 68, k = i % 68, seg = k / 17, t = k % 17;
        int off = (seg == 0) ? t : (seg == 1) ? 16*17 + t : (seg == 2) ? t*17 : t*17 + 16;
        s->B.p1p[ch * 289 + off] = 0.f;
    }
    for (int i = tid; i < 600; i += NT) {
        int oc = i / 75, r = i % 75;
        float v = gw1[i];
        s->w1d[r * 8 + oc] = make_float2(v, v);
    }
    for (int i = tid; i < 1152; i += NT) {
        int oc = i / 72, r = i % 72;
        s->w2f[r * 16 + oc] = gw2[i];
    }
    // w3p interleaved
    for (int i = tid; i < 512; i += NT) {
        int oc = i >> 4, ic = i & 15;
        int u = (ic >> 1) * 32 + ((oc & 15) >> 1) * 4 + (oc >> 4) * 2 + (oc & 1);
        ((float*)s->w3p)[u * 2 + (ic & 1)] = gw3[i];
    }
    // wcfcT[p][oc] = w_cfc[oc*16 + p]
    for (int i = tid; i < 1024; i += NT) {
        int p = i >> 6, c = i & 63;
        s->wcfcT[p * 64 + c] = gwcfc[c * 16 + p];
    }
    for (int i = tid; i < 64; i += NT) s->bcf[i] = gbcf[i];
    if (tid < 8)  s->b1[tid] = gb1[tid];
    if (tid < 16) s->b2[tid] = gb2[tid];
    if (tid < 32) s->b3[tid] = gb3[tid];
    if (tid == 0) s->bcfc = gbcfc[0];
    __syncthreads();

    // ---- Phase 1: x -> padded smem (LDG.128) ----
    const float* xin = gx + (size_t)b * 3072;
    for (int i4 = tid; i4 < 768; i4 += NT) {
        float4 v = *(const float4*)&xin[i4 * 4];
        int i = i4 * 4;
        int c = i >> 10, r = (i >> 5) & 31, cc = i & 31;
        float* dst = &s->A.xs[c * 1156 + (r + 1) * 34 + (cc + 1)];
        dst[0] = v.x; dst[1] = v.y; dst[2] = v.z; dst[3] = v.w;
    }
    __syncthreads();

    // ---- Phase 2: conv1 (3->8, 5x5) + relu + maxpool2, 2 oc-passes, rolling rows ----
    if (tid < 225) {
        const int py = tid / 15, px = tid % 15;
        const int x0 = 2 * px, y0 = 2 * py;
        #pragma unroll
        for (int h = 0; h < 2; h++) {
            u64 acc[4][2];
            #pragma unroll
            for (int k = 0; k < 4; k++) { acc[k][0] = 0ull; acc[k][1] = 0ull; }
            #pragma unroll
            for (int ic = 0; ic < 3; ic++) {
                const float* xb = &s->A.xs[ic * 1156 + y0 * 34 + x0];
                const u64* pr = (const u64*)xb;
                u64 C0 = pr[0], C1 = pr[1], C2 = pr[2];
                float cl0,ch0,cl1,ch1,cl2,ch2;
                upk2(C0,cl0,ch0); upk2(C1,cl1,ch1); upk2(C2,cl2,ch2);
                u64 cur[5] = { C0, pk2(ch0, cl1), C1, pk2(ch1, cl2), C2 };
                #pragma unroll
                for (int ky = 0; ky < 5; ky++) {
                    const u64* pn = (const u64*)(xb + (ky + 1) * 34);
                    u64 N0 = pn[0], N1 = pn[1], N2 = pn[2];
                    float nl0,nh0,nl1,nh1,nl2,nh2;
                    upk2(N0,nl0,nh0); upk2(N1,nl1,nh1); upk2(N2,nl2,nh2);
                    u64 nxt[5] = { N0, pk2(nh0, nl1), N1, pk2(nh1, nl2), N2 };
                    const ulonglong2* wp =
                        (const ulonglong2*)&s->w1d[(ic * 25 + ky * 5) * 8 + h * 4];
                    #pragma unroll
                    for (int kx = 0; kx < 5; kx++) {
                        #pragma unroll
                        for (int j = 0; j < 2; j++) {
                            ulonglong2 w2 = wp[kx * 4 + j];
                            fma2(acc[2*j  ][0], w2.x, cur[kx]);
                            fma2(acc[2*j  ][1], w2.x, nxt[kx]);
                            fma2(acc[2*j+1][0], w2.y, cur[kx]);
                            fma2(acc[2*j+1][1], w2.y, nxt[kx]);
                        }
                    }
                    #pragma unroll
                    for (int q = 0; q < 5; q++) cur[q] = nxt[q];
                }
            }
            #pragma unroll
            for (int k = 0; k < 4; k++) {
                float a0, a1, c0, c1;
                upk2(acc[k][0], a0, a1); upk2(acc[k][1], c0, c1);
                float m = fmaxf(fmaxf(a0, a1), fmaxf(c0, c1)) + s->b1[h * 4 + k];
                s->B.p1p[(h * 4 + k) * 289 + (py + 1) * 17 + (px + 1)] = fmaxf(m, 0.f);
            }
        }
    }
    __syncthreads();

    // ---- Phase 2.5 (xs dead): wcfp interleaved fill + conv2 (rolling rows) ----
    for (int i = tid; i < 1024; i += NT) {
        int icp = i >> 6, oc = i & 63;
        int slot = icp * 64 + ((oc >> 1) & 1) * 32 + (oc >> 5) * 16
                 + ((oc >> 2) & 7) * 2 + (oc & 1);
        s->A.wcfp[slot] = pk2(gwcf[oc * 32 + 2 * icp], gwcf[oc * 32 + 2 * icp + 1]);
    }
    if (tid < 196) {
        const int ocg = tid / 49;
        const int pos = tid % 49;
        const int py = pos / 7, px = pos % 7;
        u64 acc[4][2];
        #pragma unroll
        for (int k = 0; k < 4; k++) { acc[k][0] = 0ull; acc[k][1] = 0ull; }
        #pragma unroll
        for (int ic = 0; ic < 8; ic++) {
            const float* pbase = &s->B.p1p[ic * 289 + 2 * py * 17 + 2 * px];
            float a0 = pbase[0], a1 = pbase[1], a2 = pbase[2], a3 = pbase[3];
            u64 cur[3] = { pk2(a0, a1), pk2(a1, a2), pk2(a2, a3) };
            #pragma unroll
            for (int ky = 0; ky < 3; ky++) {
                const float* pn = pbase + (ky + 1) * 17;
                float n0 = pn[0], n1 = pn[1], n2 = pn[2], n3 = pn[3];
                u64 nxt[3] = { pk2(n0, n1), pk2(n1, n2), pk2(n2, n3) };
                #pragma unroll
                for (int kx = 0; kx < 3; kx++) {
                    float4 wv = *(const float4*)
                        &s->w2f[(ic * 9 + ky * 3 + kx) * 16 + ocg * 4];
                    u64 d0 = pk2(wv.x, wv.x), d1 = pk2(wv.y, wv.y);
                    u64 d2 = pk2(wv.z, wv.z), d3 = pk2(wv.w, wv.w);
                    fma2(acc[0][0], d0, cur[kx]); fma2(acc[0][1], d0, nxt[kx]);
                    fma2(acc[1][0], d1, cur[kx]); fma2(acc[1][1], d1, nxt[kx]);
                    fma2(acc[2][0], d2, cur[kx]); fma2(acc[2][1], d2, nxt[kx]);
                    fma2(acc[3][0], d3, cur[kx]); fma2(acc[3][1], d3, nxt[kx]);
                }
                #pragma unroll
                for (int q = 0; q < 3; q++) cur[q] = nxt[q];
            }
        }
        #pragma unroll
        for (int k = 0; k < 4; k++) {
            float a0, a1, c0, c1;
            upk2(acc[k][0], a0, a1); upk2(acc[k][1], c0, c1);
            float m = fmaxf(fmaxf(a0, a1), fmaxf(c0, c1)) + s->b2[ocg * 4 + k];
            s->C.p2[(ocg * 4 + k) * 49 + pos] = fmaxf(m, 0.f);
        }
    }
    __syncthreads();

    // ---- Phase 3.5 (p1p dead): weffp interleaved fill + conv3 -> ftp ----
    for (int o = tid; o < 1024; o += NT) {
        int oc = o >> 5, ic = o & 31;
        float v = __ldg(&gwa[oc * 48 + 16 + ic]);
        #pragma unroll
        for (int j = 0; j < 16; j++)
            v += __ldg(&gwa[oc * 48 + j]) * __ldg(&gwq[j * 32 + ic]);
        int slot = (ic >> 1) * 32 + ((oc >> 1) & 1) * 16 + ((oc >> 2) & 7) * 2 + (oc & 1);
        ((float*)s->B.L.weffp)[slot * 2 + (ic & 1)] = v;
    }
    if (tid < 32) {
        float v = __ldg(&gba[tid]);
        #pragma unroll
        for (int j = 0; j < 16; j++)
            v += __ldg(&gwa[tid * 48 + j]) * __ldg(&gbq[j]);
        s->B.L.beff[tid] = v;
    }
    // conv3: thread = (pos 0..95, half of 16 oc), 2 passes of 8 oc
    if (tid < 192) {
        const int pos  = tid >> 1;
        const int half = tid & 1;
        const int y = pos / 10, x = pos % 10;
        const bool valid_cell = (x < 9) && (y < 9);
        const bool interior = ((unsigned)(y - 1) < 7u) && ((unsigned)(x - 1) < 7u);
        if (interior) {
            const int pidx = (y - 1) * 7 + (x - 1);
            #pragma unroll
            for (int hp = 0; hp < 2; hp++) {
                u64 acc[8];
                #pragma unroll
                for (int k = 0; k < 8; k++) acc[k] = 0ull;
                #pragma unroll
                for (int icp = 0; icp < 8; icp++) {
                    u64 fd = pk2(s->C.p2[(2 * icp) * 49 + pidx],
                                 s->C.p2[(2 * icp + 1) * 49 + pidx]);
                    const ulonglong2* wp =
                        (const ulonglong2*)&s->w3p[icp * 32 + half * 2];
                    #pragma unroll
                    for (int j = 0; j < 4; j++) {
                        ulonglong2 w2 = wp[(hp * 4 + j) * 2];
                        fma2(acc[2*j],   w2.x, fd);
                        fma2(acc[2*j+1], w2.y, fd);
                    }
                }
                #pragma unroll
                for (int jp = 0; jp < 4; jp++)
                    s->ftp[(half * 8 + hp * 4 + jp) * FTS + pos] =
                        pk2(hsum2(acc[2*jp])   + s->b3[half*16 + hp*8 + 2*jp],
                            hsum2(acc[2*jp+1]) + s->b3[half*16 + hp*8 + 2*jp + 1]);
            }
        } else {
            #pragma unroll
            for (int jp = 0; jp < 8; jp++)
                s->ftp[(half * 8 + jp) * FTS + pos] =
                    valid_cell ? pk2(s->b3[half * 16 + 2*jp], s->b3[half * 16 + 2*jp + 1])
                               : 0ull;
        }
    }
    __syncthreads();

    // ---- depth-loop roles (4 oc x 4 pos per lane) ----
    const int o8c = lane >> 2;          // oc-quad index 0..7
    const int gc  = lane & 3;           // pos-group 0..3
    const int pq = wid >> 1, ochalf = wid & 1;
    const int cbase = (2 * pq) * 10 + 2 * gc;   // u64 pos of pool-quad row0 pair
    const int pposc = pq * 4 + gc;              // pooled position
    const int ocbc  = ochalf * 32 + o8c * 4;    // conf oc base
    const int posa = wid * 16 + 2 * gc;
    const int ocba = o8c * 4;
    const bool aact = wid < 6;

    // ---- Phase 5: adaptive depth loop ----
    for (int depth = 0; depth < 8; depth++) {
        // --- conf head: GEMM (lane = pool quad x 4 oc) -> lane-local pool -> red ---
        {
            u64 cacc[4][4];
            #pragma unroll
            for (int j = 0; j < 4; j++)
                #pragma unroll
                for (int k = 0; k < 4; k++) cacc[j][k] = 0ull;
            #pragma unroll 8
            for (int icp = 0; icp < 16; icp++) {
                const u64* fb = &s->ftp[icp * FTS + cbase];
                ulonglong2 f0 = *(const ulonglong2*)fb;          // row 2pq
                ulonglong2 f1 = *(const ulonglong2*)(fb + 10);   // row 2pq+1
                const ulonglong2* wp =
                    (const ulonglong2*)&s->A.wcfp[icp * 64 + ochalf * 16 + o8c * 2];
                ulonglong2 wA = wp[0], wB = wp[16];
                fma2(cacc[0][0], wA.x, f0.x); fma2(cacc[0][1], wA.x, f0.y);
                fma2(cacc[0][2], wA.x, f1.x); fma2(cacc[0][3], wA.x, f1.y);
                fma2(cacc[1][0], wA.y, f0.x); fma2(cacc[1][1], wA.y, f0.y);
                fma2(cacc[1][2], wA.y, f1.x); fma2(cacc[1][3], wA.y, f1.y);
                fma2(cacc[2][0], wB.x, f0.x); fma2(cacc[2][1], wB.x, f0.y);
                fma2(cacc[2][2], wB.x, f1.x); fma2(cacc[2][3], wB.x, f1.y);
                fma2(cacc[3][0], wB.y, f0.x); fma2(cacc[3][1], wB.y, f0.y);
                fma2(cacc[3][2], wB.y, f1.x); fma2(cacc[3][3], wB.y, f1.y);
            }
            float4 bcv = *(const float4*)&s->bcf[ocbc];
            float4 wfc = *(const float4*)&s->wcfcT[pposc * 64 + ocbc];
            const float bv[4] = {bcv.x, bcv.y, bcv.z, bcv.w};
            const float wv[4] = {wfc.x, wfc.y, wfc.z, wfc.w};
            float partial = 0.f;
            #pragma unroll
            for (int j = 0; j < 4; j++) {
                float m = fmaxf(fmaxf(hsum2(cacc[j][0]), hsum2(cacc[j][1])),
                                fmaxf(hsum2(cacc[j][2]), hsum2(cacc[j][3]))) + bv[j];
                m = fmaxf(m, 0.f);
                partial += m * wv[j];
            }
            #pragma unroll
            for (int o = 16; o > 0; o >>= 1)
                partial += __shfl_down_sync(0xffffffffu, partial, o);
            if (lane == 0) s->C.R.red[wid] = partial;
        }

        // --- a-conv accumulate (warps 0-5) ---
        u64 acc[4][4];
        if (aact) {
            #pragma unroll
            for (int j = 0; j < 4; j++)
                #pragma unroll
                for (int k = 0; k < 4; k++) acc[j][k] = 0ull;
            #pragma unroll 8
            for (int icp = 0; icp < 16; icp++) {
                const u64* fb = &s->ftp[icp * FTS + posa];
                ulonglong2 fA = *(const ulonglong2*)fb;          // pos 2g, 2g+1
                ulonglong2 fB = *(const ulonglong2*)(fb + 8);    // pos 2g+8, 2g+9
                const ulonglong2* wp =
                    (const ulonglong2*)&s->B.L.weffp[icp * 32 + o8c * 2];
                ulonglong2 wA = wp[0], wB = wp[8];
                fma2(acc[0][0], wA.x, fA.x); fma2(acc[0][1], wA.x, fA.y);
                fma2(acc[0][2], wA.x, fB.x); fma2(acc[0][3], wA.x, fB.y);
                fma2(acc[1][0], wA.y, fA.x); fma2(acc[1][1], wA.y, fA.y);
                fma2(acc[1][2], wA.y, fB.x); fma2(acc[1][3], wA.y, fB.y);
                fma2(acc[2][0], wB.x, fA.x); fma2(acc[2][1], wB.x, fA.y);
                fma2(acc[2][2], wB.x, fB.x); fma2(acc[2][3], wB.x, fB.y);
                fma2(acc[3][0], wB.y, fA.x); fma2(acc[3][1], wB.y, fA.y);
                fma2(acc[3][2], wB.y, fB.x); fma2(acc[3][3], wB.y, fB.y);
            }
        }
        __syncthreads();   // red visible + all ftp reads complete

        // --- decision: every thread computes the logit (uniform) ---
        {
            float4 r0 = *(const float4*)&s->C.R.red[0];
            float4 r1 = *(const float4*)&s->C.R.red[4];
            float logit = s->bcfc + r0.x + r0.y + r0.z + r0.w
                                  + r1.x + r1.y + r1.z + r1.w;
            if (logit >= 2.1972245773362196f) break;   // conf >= 0.9 -> frozen
        }

        // --- apply residual: ftp += tanh(acc + beff) ---
        if (aact) {
            float4 bvv = *(const float4*)&s->B.L.beff[ocba];
            #pragma unroll
            for (int h = 0; h < 2; h++) {       // position-pair offset 0 / +8
                ulonglong2* p0 = (ulonglong2*)&s->ftp[(2 * o8c) * FTS + posa + 8 * h];
                ulonglong2 v0 = *p0;
                float e0, e1, f0, f1;
                upk2(v0.x, e0, e1); upk2(v0.y, f0, f1);
                v0.x = pk2(e0 + fast_tanh(hsum2(acc[0][2*h])     + bvv.x),
                           e1 + fast_tanh(hsum2(acc[1][2*h])     + bvv.y));
                v0.y = pk2(f0 + fast_tanh(hsum2(acc[0][2*h + 1]) + bvv.x),
                           f1 + fast_tanh(hsum2(acc[1][2*h + 1]) + bvv.y));
                *p0 = v0;
                ulonglong2* p1 = (ulonglong2*)&s->ftp[(2 * o8c + 1) * FTS + posa + 8 * h];
                ulonglong2 v1 = *p1;
                upk2(v1.x, e0, e1); upk2(v1.y, f0, f1);
                v1.x = pk2(e0 + fast_tanh(hsum2(acc[2][2*h])     + bvv.z),
                           e1 + fast_tanh(hsum2(acc[3][2*h])     + bvv.w));
                v1.y = pk2(f0 + fast_tanh(hsum2(acc[2][2*h + 1]) + bvv.z),
                           f1 + fast_tanh(hsum2(acc[3][2*h + 1]) + bvv.w));
                *p1 = v1;
            }
        }
        __syncthreads();   // writes visible before next depth's reads
    }

    // ---- Phase 6: classifier (float4 LDG over w_cls) ----
    {
        const float* ftf = (const float*)s->ftp;
        float ac[10];
        #pragma unroll
        for (int o = 0; o < 10; o++) ac[o] = 0.f;
        #pragma unroll
        for (int k = 0; k < 3; k++) {
            int i4 = tid + k * NT;
            if (i4 < 648) {
                int i = i4 * 4;
                float fv[4];
                #pragma unroll
                for (int t = 0; t < 4; t++) {
                    int ii = i + t;
                    int ch = ii / 81;
                    int r  = ii - ch * 81;
                    int y  = r / 9, x = r - 9 * y;
                    fv[t] = ftf[(ch >> 1) * (2 * FTS) + (y * 10 + x) * 2 + (ch & 1)];
                }
                #pragma unroll
                for (int o = 0; o < 10; o++) {
                    float4 w4 = *(const float4*)&gwcls[o * 2592 + i];
                    ac[o] += w4.x * fv[0] + w4.y * fv[1] + w4.z * fv[2] + w4.w * fv[3];
                }
            }
        }
        #pragma unroll
        for (int o = 0; o < 10; o++) {
            float v = ac[o];
            #pragma unroll
            for (int sh = 16; sh > 0; sh >>= 1)
                v += __shfl_down_sync(0xffffffffu, v, sh);
            if (lane == 0) s->C.R.clsred[wid * 10 + o] = v;
        }
        __syncthreads();
        if (tid < 10) {
            float v = gbcls[tid];
            #pragma unroll
            for (int w = 0; w < 8; w++) v += s->C.R.clsred[w * 10 + tid];
            gout[(size_t)b * 10 + tid] = v;
        }
    }
}

extern "C" void kernel_launch(void* const* d_in, const int* in_sizes, int n_in,
                              void* d_out, int out_size) {
    const float* x     = (const float*)d_in[0];
    const float* w_b1  = (const float*)d_in[1];
    const float* b_b1  = (const float*)d_in[2];
    const float* w_b2  = (const float*)d_in[3];
    const float* b_b2  = (const float*)d_in[4];
    const float* w_b3  = (const float*)d_in[5];
    const float* b_b3  = (const float*)d_in[6];
    const float* w_cf  = (const float*)d_in[7];
    const float* b_cf  = (const float*)d_in[8];
    const float* w_cfc = (const float*)d_in[9];
    const float* b_cfc = (const float*)d_in[10];
    const float* w_q   = (const float*)d_in[11];
    const float* b_q   = (const float*)d_in[12];
    const float* w_a   = (const float*)d_in[13];
    const float* b_a   = (const float*)d_in[14];
    const float* w_cls = (const float*)d_in[15];
    const float* b_cls = (const float*)d_in[16];
    float* out = (float*)d_out;

    int B = in_sizes[0] / (3 * 32 * 32);
    size_t smem = sizeof(Smem);
    cudaFuncSetAttribute(TM_20005957665089_kernel,
                         cudaFuncAttributeMaxDynamicSharedMemorySize, (int)smem);
    TM_20005957665089_kernel<<<B, NT, smem>>>(
        x, w_b1, b_b1, w_b2, b_b2, w_b3, b_b3,
        w_cf, b_cf, w_cfc, b_cfc, w_q, b_q, w_a, b_a,
        w_cls, b_cls, out);
}

// round 15
// speedup vs baseline: 1.1718x; 1.1718x over previous
#include <cuda_runtime.h>
#include <math.h>

#define NT 256
#define FTS 98    // ftp row stride in u64 (784B)
typedef unsigned long long u64;

__device__ __forceinline__ u64 pk2(float lo, float hi) {
    u64 r; asm("mov.b64 %0,{%1,%2};" : "=l"(r) : "f"(lo), "f"(hi)); return r;
}
__device__ __forceinline__ void upk2(u64 v, float& lo, float& hi) {
    asm("mov.b64 {%0,%1},%2;" : "=f"(lo), "=f"(hi) : "l"(v));
}
__device__ __forceinline__ void fma2(u64& d, u64 a, u64 b) {
    asm("fma.rn.f32x2 %0,%1,%2,%0;" : "+l"(d) : "l"(a), "l"(b));
}
__device__ __forceinline__ float hsum2(u64 v) {
    float lo, hi; upk2(v, lo, hi); return lo + hi;
}
__device__ __forceinline__ float fast_tanh(float x) {
    float t, r;
    asm("ex2.approx.f32 %0, %1;" : "=f"(t) : "f"(x * 2.885390082f));
    asm("rcp.approx.f32 %0, %1;" : "=f"(r) : "f"(t + 1.0f));
    return 1.0f - 2.0f * r;
}

struct __align__(16) Smem {
    union {
        float xs[3 * 34 * 34];       // phases 1-2 (13872B)
        u64   wcfp[16 * 64];         // depth loop: [icp][chunk][half][o8] pairs (8192B)
    } A;
    union {
        float p1p[8 * 17 * 17];      // phases 2-3 (9248B)
        struct { u64 weffp[16 * 32]; float beff[32]; } L;  // depth loop (4224B)
    } B;
    union {
        float p2[16 * 49];           // phases 3-4 (3136B)
        struct { float red[8]; float clsred[80]; } R;      // depth loop + classifier
    } C;
    u64    ftp[16 * FTS];            // feature map [icp][pos], pos = y*10+x (12544B)
    float2 w1d[600];                 // conv1 [tap][oc8] dup pairs (4800B)
    float  w2f[72 * 16];             // conv2 [tap][oc] plain floats (4608B)
    u64    w3p[8 * 32];              // conv3 [icp][j][half] interleaved (2048B)
    float  wcfcT[16 * 64];           // conf fc weights transposed [pooledpos][oc] (4096B)
    float  bcf[64];
    float  b1[8], b2[16], b3[32];
    float  bcfc;
};

__global__ __launch_bounds__(NT, 4)
void TM_20005957665089_kernel(
    const float* __restrict__ gx,
    const float* __restrict__ gw1,  const float* __restrict__ gb1,
    const float* __restrict__ gw2,  const float* __restrict__ gb2,
    const float* __restrict__ gw3,  const float* __restrict__ gb3,
    const float* __restrict__ gwcf, const float* __restrict__ gbcf,
    const float* __restrict__ gwcfc,const float* __restrict__ gbcfc,
    const float* __restrict__ gwq,  const float* __restrict__ gbq,
    const float* __restrict__ gwa,  const float* __restrict__ gba,
    const float* __restrict__ gwcls,const float* __restrict__ gbcls,
    float* __restrict__ gout)
{
    extern __shared__ float smem_raw[];
    Smem* s = reinterpret_cast<Smem*>(smem_raw);
    const int tid  = threadIdx.x;
    const int lane = tid & 31;
    const int wid  = tid >> 5;
    const int b    = blockIdx.x;

    // ---- Phase 0: border-only zeroing + weight staging ----
    for (int i = tid; i < 408; i += NT) {   // xs border ring (interior overwritten)
        int ch = i / 136, k = i % 136, seg = k / 34, t = k % 34;
        int off = (seg == 0) ? t : (seg == 1) ? 33*34 + t : (seg == 2) ? t*34 : t*34 + 33;
        s->A.xs[ch * 1156 + off] = 0.f;
    }
    for (int i = tid; i < 544; i += NT) {   // p1p border ring
        int ch = i / 68, k = i % 68, seg = k / 17, t = k % 17;
        int off = (seg == 0) ? t : (seg == 1) ? 16*17 + t : (seg == 2) ? t*17 : t*17 + 16;
        s->B.p1p[ch * 289 + off] = 0.f;
    }
    for (int i = tid; i < 600; i += NT) {
        int oc = i / 75, r = i % 75;
        float v = gw1[i];
        s->w1d[r * 8 + oc] = make_float2(v, v);
    }
    for (int i = tid; i < 1152; i += NT) {
        int oc = i / 72, r = i % 72;
        s->w2f[r * 16 + oc] = gw2[i];
    }
    // w3p interleaved
    for (int i = tid; i < 512; i += NT) {
        int oc = i >> 4, ic = i & 15;
        int u = (ic >> 1) * 32 + ((oc & 15) >> 1) * 4 + (oc >> 4) * 2 + (oc & 1);
        ((float*)s->w3p)[u * 2 + (ic & 1)] = gw3[i];
    }
    // wcfcT[p][oc] = w_cfc[oc*16 + p]
    for (int i = tid; i < 1024; i += NT) {
        int p = i >> 6, c = i & 63;
        s->wcfcT[p * 64 + c] = gwcfc[c * 16 + p];
    }
    for (int i = tid; i < 64; i += NT) s->bcf[i] = gbcf[i];
    if (tid < 8)  s->b1[tid] = gb1[tid];
    if (tid < 16) s->b2[tid] = gb2[tid];
    if (tid < 32) s->b3[tid] = gb3[tid];
    if (tid == 0) s->bcfc = gbcfc[0];
    __syncthreads();

    // ---- Phase 1: x -> padded smem (LDG.128) ----
    const float* xin = gx + (size_t)b * 3072;
    for (int i4 = tid; i4 < 768; i4 += NT) {
        float4 v = *(const float4*)&xin[i4 * 4];
        int i = i4 * 4;
        int c = i >> 10, r = (i >> 5) & 31, cc = i & 31;
        float* dst = &s->A.xs[c * 1156 + (r + 1) * 34 + (cc + 1)];
        dst[0] = v.x; dst[1] = v.y; dst[2] = v.z; dst[3] = v.w;
    }
    __syncthreads();

    // ---- Phase 2: conv1 (3->8, 5x5) + relu + maxpool2, 2 oc-passes, rolling rows ----
    if (tid < 225) {
        const int py = tid / 15, px = tid % 15;
        const int x0 = 2 * px, y0 = 2 * py;
        #pragma unroll
        for (int h = 0; h < 2; h++) {
            u64 acc[4][2];
            #pragma unroll
            for (int k = 0; k < 4; k++) { acc[k][0] = 0ull; acc[k][1] = 0ull; }
            #pragma unroll
            for (int ic = 0; ic < 3; ic++) {
                const float* xb = &s->A.xs[ic * 1156 + y0 * 34 + x0];
                const u64* pr = (const u64*)xb;
                u64 C0 = pr[0], C1 = pr[1], C2 = pr[2];
                float cl0,ch0,cl1,ch1,cl2,ch2;
                upk2(C0,cl0,ch0); upk2(C1,cl1,ch1); upk2(C2,cl2,ch2);
                u64 cur[5] = { C0, pk2(ch0, cl1), C1, pk2(ch1, cl2), C2 };
                #pragma unroll
                for (int ky = 0; ky < 5; ky++) {
                    const u64* pn = (const u64*)(xb + (ky + 1) * 34);
                    u64 N0 = pn[0], N1 = pn[1], N2 = pn[2];
                    float nl0,nh0,nl1,nh1,nl2,nh2;
                    upk2(N0,nl0,nh0); upk2(N1,nl1,nh1); upk2(N2,nl2,nh2);
                    u64 nxt[5] = { N0, pk2(nh0, nl1), N1, pk2(nh1, nl2), N2 };
                    const ulonglong2* wp =
                        (const ulonglong2*)&s->w1d[(ic * 25 + ky * 5) * 8 + h * 4];
                    #pragma unroll
                    for (int kx = 0; kx < 5; kx++) {
                        #pragma unroll
                        for (int j = 0; j < 2; j++) {
                            ulonglong2 w2 = wp[kx * 4 + j];
                            fma2(acc[2*j  ][0], w2.x, cur[kx]);
                            fma2(acc[2*j  ][1], w2.x, nxt[kx]);
                            fma2(acc[2*j+1][0], w2.y, cur[kx]);
                            fma2(acc[2*j+1][1], w2.y, nxt[kx]);
                        }
                    }
                    #pragma unroll
                    for (int q = 0; q < 5; q++) cur[q] = nxt[q];
                }
            }
            #pragma unroll
            for (int k = 0; k < 4; k++) {
                float a0, a1, c0, c1;
                upk2(acc[k][0], a0, a1); upk2(acc[k][1], c0, c1);
                float m = fmaxf(fmaxf(a0, a1), fmaxf(c0, c1)) + s->b1[h * 4 + k];
                s->B.p1p[(h * 4 + k) * 289 + (py + 1) * 17 + (px + 1)] = fmaxf(m, 0.f);
            }
        }
    }
    __syncthreads();

    // ---- Phase 2.5 (xs dead): wcfp interleaved fill + conv2 (rolling rows) ----
    for (int i = tid; i < 1024; i += NT) {
        int icp = i >> 6, oc = i & 63;
        int slot = icp * 64 + ((oc >> 1) & 1) * 32 + (oc >> 5) * 16
                 + ((oc >> 2) & 7) * 2 + (oc & 1);
        s->A.wcfp[slot] = pk2(gwcf[oc * 32 + 2 * icp], gwcf[oc * 32 + 2 * icp + 1]);
    }
    if (tid < 196) {
        const int ocg = tid / 49;
        const int pos = tid % 49;
        const int py = pos / 7, px = pos % 7;
        u64 acc[4][2];
        #pragma unroll
        for (int k = 0; k < 4; k++) { acc[k][0] = 0ull; acc[k][1] = 0ull; }
        #pragma unroll
        for (int ic = 0; ic < 8; ic++) {
            const float* pbase = &s->B.p1p[ic * 289 + 2 * py * 17 + 2 * px];
            float a0 = pbase[0], a1 = pbase[1], a2 = pbase[2], a3 = pbase[3];
            u64 cur[3] = { pk2(a0, a1), pk2(a1, a2), pk2(a2, a3) };
            #pragma unroll
            for (int ky = 0; ky < 3; ky++) {
                const float* pn = pbase + (ky + 1) * 17;
                float n0 = pn[0], n1 = pn[1], n2 = pn[2], n3 = pn[3];
                u64 nxt[3] = { pk2(n0, n1), pk2(n1, n2), pk2(n2, n3) };
                #pragma unroll
                for (int kx = 0; kx < 3; kx++) {
                    float4 wv = *(const float4*)
                        &s->w2f[(ic * 9 + ky * 3 + kx) * 16 + ocg * 4];
                    u64 d0 = pk2(wv.x, wv.x), d1 = pk2(wv.y, wv.y);
                    u64 d2 = pk2(wv.z, wv.z), d3 = pk2(wv.w, wv.w);
                    fma2(acc[0][0], d0, cur[kx]); fma2(acc[0][1], d0, nxt[kx]);
                    fma2(acc[1][0], d1, cur[kx]); fma2(acc[1][1], d1, nxt[kx]);
                    fma2(acc[2][0], d2, cur[kx]); fma2(acc[2][1], d2, nxt[kx]);
                    fma2(acc[3][0], d3, cur[kx]); fma2(acc[3][1], d3, nxt[kx]);
                }
                #pragma unroll
                for (int q = 0; q < 3; q++) cur[q] = nxt[q];
            }
        }
        #pragma unroll
        for (int k = 0; k < 4; k++) {
            float a0, a1, c0, c1;
            upk2(acc[k][0], a0, a1); upk2(acc[k][1], c0, c1);
            float m = fmaxf(fmaxf(a0, a1), fmaxf(c0, c1)) + s->b2[ocg * 4 + k];
            s->C.p2[(ocg * 4 + k) * 49 + pos] = fmaxf(m, 0.f);
        }
    }
    __syncthreads();

    // ---- Phase 3.5 (p1p dead): weffp interleaved fill + conv3 -> ftp ----
    for (int o = tid; o < 1024; o += NT) {
        int oc = o >> 5, ic = o & 31;
        float v = __ldg(&gwa[oc * 48 + 16 + ic]);
        #pragma unroll
        for (int j = 0; j < 16; j++)
            v += __ldg(&gwa[oc * 48 + j]) * __ldg(&gwq[j * 32 + ic]);
        int slot = (ic >> 1) * 32 + ((oc >> 1) & 1) * 16 + ((oc >> 2) & 7) * 2 + (oc & 1);
        ((float*)s->B.L.weffp)[slot * 2 + (ic & 1)] = v;
    }
    if (tid < 32) {
        float v = __ldg(&gba[tid]);
        #pragma unroll
        for (int j = 0; j < 16; j++)
            v += __ldg(&gwa[tid * 48 + j]) * __ldg(&gbq[j]);
        s->B.L.beff[tid] = v;
    }
    // conv3: thread = (pos 0..95, half of 16 oc), 2 passes of 8 oc
    if (tid < 192) {
        const int pos  = tid >> 1;
        const int half = tid & 1;
        const int y = pos / 10, x = pos % 10;
        const bool valid_cell = (x < 9) && (y < 9);
        const bool interior = ((unsigned)(y - 1) < 7u) && ((unsigned)(x - 1) < 7u);
        if (interior) {
            const int pidx = (y - 1) * 7 + (x - 1);
            #pragma unroll
            for (int hp = 0; hp < 2; hp++) {
                u64 acc[8];
                #pragma unroll
                for (int k = 0; k < 8; k++) acc[k] = 0ull;
                #pragma unroll
                for (int icp = 0; icp < 8; icp++) {
                    u64 fd = pk2(s->C.p2[(2 * icp) * 49 + pidx],
                                 s->C.p2[(2 * icp + 1) * 49 + pidx]);
                    const ulonglong2* wp =
                        (const ulonglong2*)&s->w3p[icp * 32 + half * 2];
                    #pragma unroll
                    for (int j = 0; j < 4; j++) {
                        ulonglong2 w2 = wp[(hp * 4 + j) * 2];
                        fma2(acc[2*j],   w2.x, fd);
                        fma2(acc[2*j+1], w2.y, fd);
                    }
                }
                #pragma unroll
                for (int jp = 0; jp < 4; jp++)
                    s->ftp[(half * 8 + hp * 4 + jp) * FTS + pos] =
                        pk2(hsum2(acc[2*jp])   + s->b3[half*16 + hp*8 + 2*jp],
                            hsum2(acc[2*jp+1]) + s->b3[half*16 + hp*8 + 2*jp + 1]);
            }
        } else {
            #pragma unroll
            for (int jp = 0; jp < 8; jp++)
                s->ftp[(half * 8 + jp) * FTS + pos] =
                    valid_cell ? pk2(s->b3[half * 16 + 2*jp], s->b3[half * 16 + 2*jp + 1])
                               : 0ull;
        }
    }
    __syncthreads();

    // ---- depth-loop roles (4 oc x 4 pos per lane) ----
    const int o8c = lane >> 2;          // oc-quad index 0..7
    const int gc  = lane & 3;           // pos-group 0..3
    const int pq = wid >> 1, ochalf = wid & 1;
    const int cbase = (2 * pq) * 10 + 2 * gc;   // u64 pos of pool-quad row0 pair
    const int pposc = pq * 4 + gc;              // pooled position
    const int ocbc  = ochalf * 32 + o8c * 4;    // conf oc base
    const int posa = wid * 16 + 2 * gc;
    const int ocba = o8c * 4;
    const bool aact = wid < 6;

    // ---- Phase 5: adaptive depth loop ----
    for (int depth = 0; depth < 8; depth++) {
        // --- conf head: GEMM (lane = pool quad x 4 oc) -> lane-local pool -> red ---
        {
            u64 cacc[4][4];
            #pragma unroll
            for (int j = 0; j < 4; j++)
                #pragma unroll
                for (int k = 0; k < 4; k++) cacc[j][k] = 0ull;
            #pragma unroll 4
            for (int icp = 0; icp < 16; icp++) {
                const u64* fb = &s->ftp[icp * FTS + cbase];
                ulonglong2 f0 = *(const ulonglong2*)fb;          // row 2pq
                ulonglong2 f1 = *(const ulonglong2*)(fb + 10);   // row 2pq+1
                const ulonglong2* wp =
                    (const ulonglong2*)&s->A.wcfp[icp * 64 + ochalf * 16 + o8c * 2];
                ulonglong2 wA = wp[0], wB = wp[16];
                fma2(cacc[0][0], wA.x, f0.x); fma2(cacc[0][1], wA.x, f0.y);
                fma2(cacc[0][2], wA.x, f1.x); fma2(cacc[0][3], wA.x, f1.y);
                fma2(cacc[1][0], wA.y, f0.x); fma2(cacc[1][1], wA.y, f0.y);
                fma2(cacc[1][2], wA.y, f1.x); fma2(cacc[1][3], wA.y, f1.y);
                fma2(cacc[2][0], wB.x, f0.x); fma2(cacc[2][1], wB.x, f0.y);
                fma2(cacc[2][2], wB.x, f1.x); fma2(cacc[2][3], wB.x, f1.y);
                fma2(cacc[3][0], wB.y, f0.x); fma2(cacc[3][1], wB.y, f0.y);
                fma2(cacc[3][2], wB.y, f1.x); fma2(cacc[3][3], wB.y, f1.y);
            }
            float4 bcv = *(const float4*)&s->bcf[ocbc];
            float4 wfc = *(const float4*)&s->wcfcT[pposc * 64 + ocbc];
            const float bv[4] = {bcv.x, bcv.y, bcv.z, bcv.w};
            const float wv[4] = {wfc.x, wfc.y, wfc.z, wfc.w};
            float partial = 0.f;
            #pragma unroll
            for (int j = 0; j < 4; j++) {
                float m = fmaxf(fmaxf(hsum2(cacc[j][0]), hsum2(cacc[j][1])),
                                fmaxf(hsum2(cacc[j][2]), hsum2(cacc[j][3]))) + bv[j];
                m = fmaxf(m, 0.f);
                partial += m * wv[j];
            }
            #pragma unroll
            for (int o = 16; o > 0; o >>= 1)
                partial += __shfl_down_sync(0xffffffffu, partial, o);
            if (lane == 0) s->C.R.red[wid] = partial;
        }

        // --- a-conv accumulate (warps 0-5) ---
        u64 acc[4][4];
        #pragma unroll
        for (int j = 0; j < 4; j++)
            #pragma unroll
            for (int k = 0; k < 4; k++) acc[j][k] = 0ull;
        if (aact) {
            #pragma unroll 4
            for (int icp = 0; icp < 16; icp++) {
                const u64* fb = &s->ftp[icp * FTS + posa];
                ulonglong2 fA = *(const ulonglong2*)fb;          // pos 2g, 2g+1
                ulonglong2 fB = *(const ulonglong2*)(fb + 8);    // pos 2g+8, 2g+9
                const ulonglong2* wp =
                    (const ulonglong2*)&s->B.L.weffp[icp * 32 + o8c * 2];
                ulonglong2 wA = wp[0], wB = wp[8];
                fma2(acc[0][0], wA.x, fA.x); fma2(acc[0][1], wA.x, fA.y);
                fma2(acc[0][2], wA.x, fB.x); fma2(acc[0][3], wA.x, fB.y);
                fma2(acc[1][0], wA.y, fA.x); fma2(acc[1][1], wA.y, fA.y);
                fma2(acc[1][2], wA.y, fB.x); fma2(acc[1][3], wA.y, fB.y);
                fma2(acc[2][0], wB.x, fA.x); fma2(acc[2][1], wB.x, fA.y);
                fma2(acc[2][2], wB.x, fB.x); fma2(acc[2][3], wB.x, fB.y);
                fma2(acc[3][0], wB.y, fA.x); fma2(acc[3][1], wB.y, fA.y);
                fma2(acc[3][2], wB.y, fB.x); fma2(acc[3][3], wB.y, fB.y);
            }
        }
        __syncthreads();   // red visible + all ftp reads complete

        // --- decision: every thread computes the logit (uniform) ---
        {
            float4 r0 = *(const float4*)&s->C.R.red[0];
            float4 r1 = *(const float4*)&s->C.R.red[4];
            float logit = s->bcfc + r0.x + r0.y + r0.z + r0.w
                                  + r1.x + r1.y + r1.z + r1.w;
            if (logit >= 2.1972245773362196f) break;   // conf >= 0.9 -> frozen
        }

        // --- apply residual: ftp += tanh(acc + beff) ---
        if (aact) {
            float4 bvv = *(const float4*)&s->B.L.beff[ocba];
            #pragma unroll
            for (int h = 0; h < 2; h++) {       // position-pair offset 0 / +8
                ulonglong2* p0 = (ulonglong2*)&s->ftp[(2 * o8c) * FTS + posa + 8 * h];
                ulonglong2 v0 = *p0;
                float e0, e1, f0, f1;
                upk2(v0.x, e0, e1); upk2(v0.y, f0, f1);
                v0.x = pk2(e0 + fast_tanh(hsum2(acc[0][2*h])     + bvv.x),
                           e1 + fast_tanh(hsum2(acc[1][2*h])     + bvv.y));
                v0.y = pk2(f0 + fast_tanh(hsum2(acc[0][2*h + 1]) + bvv.x),
                           f1 + fast_tanh(hsum2(acc[1][2*h + 1]) + bvv.y));
                *p0 = v0;
                ulonglong2* p1 = (ulonglong2*)&s->ftp[(2 * o8c + 1) * FTS + posa + 8 * h];
                ulonglong2 v1 = *p1;
                upk2(v1.x, e0, e1); upk2(v1.y, f0, f1);
                v1.x = pk2(e0 + fast_tanh(hsum2(acc[2][2*h])     + bvv.z),
                           e1 + fast_tanh(hsum2(acc[3][2*h])     + bvv.w));
                v1.y = pk2(f0 + fast_tanh(hsum2(acc[2][2*h + 1]) + bvv.z),
                           f1 + fast_tanh(hsum2(acc[3][2*h + 1]) + bvv.w));
                *p1 = v1;
            }
        }
        __syncthreads();   // writes visible before next depth's reads
    }

    // ---- Phase 6: classifier (float4 LDG over w_cls) ----
    {
        const float* ftf = (const float*)s->ftp;
        float ac[10];
        #pragma unroll
        for (int o = 0; o < 10; o++) ac[o] = 0.f;
        #pragma unroll
        for (int k = 0; k < 3; k++) {
            int i4 = tid + k * NT;
            if (i4 < 648) {
                int i = i4 * 4;
                float fv[4];
                #pragma unroll
                for (int t = 0; t < 4; t++) {
                    int ii = i + t;
                    int ch = ii / 81;
                    int r  = ii - ch * 81;
                    int y  = r / 9, x = r - 9 * y;
                    fv[t] = ftf[(ch >> 1) * (2 * FTS) + (y * 10 + x) * 2 + (ch & 1)];
                }
                #pragma unroll
                for (int o = 0; o < 10; o++) {
                    float4 w4 = *(const float4*)&gwcls[o * 2592 + i];
                    ac[o] += w4.x * fv[0] + w4.y * fv[1] + w4.z * fv[2] + w4.w * fv[3];
                }
            }
        }
        #pragma unroll
        for (int o = 0; o < 10; o++) {
            float v = ac[o];
            #pragma unroll
            for (int sh = 16; sh > 0; sh >>= 1)
                v += __shfl_down_sync(0xffffffffu, v, sh);
            if (lane == 0) s->C.R.clsred[wid * 10 + o] = v;
        }
        __syncthreads();
        if (tid < 10) {
            float v = gbcls[tid];
            #pragma unroll
            for (int w = 0; w < 8; w++) v += s->C.R.clsred[w * 10 + tid];
            gout[(size_t)b * 10 + tid] = v;
        }
    }
}

extern "C" void kernel_launch(void* const* d_in, const int* in_sizes, int n_in,
                              void* d_out, int out_size) {
    const float* x     = (const float*)d_in[0];
    const float* w_b1  = (const float*)d_in[1];
    const float* b_b1  = (const float*)d_in[2];
    const float* w_b2  = (const float*)d_in[3];
    const float* b_b2  = (const float*)d_in[4];
    const float* w_b3  = (const float*)d_in[5];
    const float* b_b3  = (const float*)d_in[6];
    const float* w_cf  = (const float*)d_in[7];
    const float* b_cf  = (const float*)d_in[8];
    const float* w_cfc = (const float*)d_in[9];
    const float* b_cfc = (const float*)d_in[10];
    const float* w_q   = (const float*)d_in[11];
    const float* b_q   = (const float*)d_in[12];
    const float* w_a   = (const float*)d_in[13];
    const float* b_a   = (const float*)d_in[14];
    const float* w_cls = (const float*)d_in[15];
    const float* b_cls = (const float*)d_in[16];
    float* out = (float*)d_out;

    int B = in_sizes[0] / (3 * 32 * 32);
    size_t smem = sizeof(Smem);
    cudaFuncSetAttribute(TM_20005957665089_kernel,
                         cudaFuncAttributeMaxDynamicSharedMemorySize, (int)smem);
    TM_20005957665089_kernel<<<B, NT, smem>>>(
        x, w_b1, b_b1, w_b2, b_b2, w_b3, b_b3,
        w_cf, b_cf, w_cfc, b_cfc, w_q, b_q, w_a, b_a,
        w_cls, b_cls, out);
}